// round 14
// baseline (speedup 1.0000x reference)
#include <cuda_runtime.h>
#include <math.h>

#define Q 256      // B*P = 4*64
#define D 768
#define NKEYS 2048
#define RADJ 12
#define TOPK 16
#define SPLITK 8
#define NB 592     // 148 SMs x occupancy 4 — forced by __launch_bounds__(256,4)

// ---------------- scratch (static device memory; no allocations) ----------------
__device__ float g_invn[NKEYS];
__device__ float g_adjsum[NKEYS * NKEYS];    // 16.8 MB
__device__ float g_scores[Q * NKEYS];        // raw dots
__device__ float g_w[Q * TOPK];
__device__ int   g_idx[Q * TOPK];
__device__ float g_nei[Q * NKEYS];
__device__ float g_opart[SPLITK * Q * D];    // 6.3 MB

// grid barrier + work-steal state (self-resetting across launches)
__device__ unsigned g_cnt = 0;
__device__ volatile unsigned g_sense = 0;
__device__ unsigned g_workA = 0;

// packed f32x2 FMA
__device__ __forceinline__ void ffma2(unsigned long long& c, unsigned long long a, unsigned long long b) {
    asm("fma.rn.f32x2 %0, %1, %2, %0;" : "+l"(c) : "l"(a), "l"(b));
}
__device__ __forceinline__ unsigned long long pack_dup(float a) {
    unsigned long long r;
    asm("mov.b64 %0, {%1, %1};" : "=l"(r) : "r"(__float_as_uint(a)));
    return r;
}

union SMem {
    struct { float As[32][68]; float Bs[32][68]; } sc;     // GEMM tiles 17.4 KB
    struct { float sv[NKEYS]; float sw[TOPK]; int sid[TOPK]; } tk;  // topk 8.2 KB
};

__device__ __forceinline__ void grid_barrier(unsigned* s_sense, int tid) {
    __syncthreads();
    if (tid == 0) {
        unsigned want = *s_sense ^ 1u;
        __threadfence();
        unsigned old = atomicAdd(&g_cnt, 1u);
        if (old == NB - 1) {
            atomicExch(&g_cnt, 0u);
            __threadfence();
            g_sense = want;                 // release
        } else {
            while (g_sense != want) { __nanosleep(32); }
        }
        __threadfence();
        *s_sense = want;
    }
    __syncthreads();
}

__global__ __launch_bounds__(256, 4) void mega_kernel(const float* __restrict__ A,
                                                      const float* __restrict__ kp,
                                                      const float* __restrict__ adj,
                                                      float* __restrict__ out) {
    __shared__ SMem sm;
    __shared__ unsigned s_sense;
    const int tid = threadIdx.x;
    const int bid = blockIdx.x;
    if (tid == 0) s_sense = g_sense;
    __syncthreads();

    // ================= PHASE A: scores GEMM + invn + adjsum (work-stealing x2) =================
    if (bid < 128) {
        // scores GEMM (NT) 64x64 tile, R5 shape (no prefetch regs — fits 64-reg cap)
        const int n0 = (bid & 31) * 64;
        const int m0 = (bid >> 5) * 64;
        const int tx = tid & 15, ty = tid >> 4;
        unsigned long long acc2[4][2] = {};
        for (int kt = 0; kt < D; kt += 32) {
            #pragma unroll
            for (int l = 0; l < 2; l++) {
                int f = tid + l * 256;
                int row = f >> 3, c4 = f & 7;
                float4 v = *(const float4*)(A + (m0 + row) * D + kt + c4 * 4);
                sm.sc.As[c4*4+0][row] = v.x; sm.sc.As[c4*4+1][row] = v.y;
                sm.sc.As[c4*4+2][row] = v.z; sm.sc.As[c4*4+3][row] = v.w;
                float4 u = *(const float4*)(kp + (n0 + row) * D + kt + c4 * 4);
                sm.sc.Bs[c4*4+0][row] = u.x; sm.sc.Bs[c4*4+1][row] = u.y;
                sm.sc.Bs[c4*4+2][row] = u.z; sm.sc.Bs[c4*4+3][row] = u.w;
            }
            __syncthreads();
            #pragma unroll
            for (int kk = 0; kk < 32; kk++) {
                float4 a4 = *(const float4*)&sm.sc.As[kk][ty * 4];
                float4 b4 = *(const float4*)&sm.sc.Bs[kk][tx * 4];
                unsigned long long bp0 = ((const unsigned long long*)&b4)[0];
                unsigned long long bp1 = ((const unsigned long long*)&b4)[1];
                float av[4] = {a4.x, a4.y, a4.z, a4.w};
                #pragma unroll
                for (int i = 0; i < 4; i++) {
                    unsigned long long ap = pack_dup(av[i]);
                    ffma2(acc2[i][0], ap, bp0);
                    ffma2(acc2[i][1], ap, bp1);
                }
            }
            __syncthreads();
        }
        #pragma unroll
        for (int i = 0; i < 4; i++) {
            float4 v;
            *(unsigned long long*)&v.x = acc2[i][0];
            *(unsigned long long*)&v.z = acc2[i][1];
            *(float4*)(g_scores + (m0 + ty * 4 + i) * NKEYS + n0 + tx * 4) = v;
        }
    } else if (bid < 384) {
        // key inverse norms: blocks 128..383, 8 warps x 256 blocks = 2048 rows
        const int row = (bid - 128) * 8 + (tid >> 5);
        const int lane = tid & 31;
        const float* src = kp + row * D;
        float s = 0.f;
        #pragma unroll
        for (int j = 0; j < D / 32; j++) { float v = src[j * 32 + lane]; s += v * v; }
        #pragma unroll
        for (int o = 16; o > 0; o >>= 1) s += __shfl_xor_sync(0xffffffffu, s, o);
        if (lane == 0) g_invn[row] = rsqrtf(s + 1e-12f);
    }
    // all blocks: steal adjsum units, 2 per grab, fused loads (MLP 24)
    {
        __shared__ unsigned s_u;
        for (;;) {
            __syncthreads();
            if (tid == 0) s_u = atomicAdd(&g_workA, 2u);
            __syncthreads();
            unsigned u = s_u;
            if (u >= 4096u) break;
            const int i0 = u * 256 + tid;
            const int i1 = i0 + 256;
            const float4* a = (const float4*)adj;
            const int stride = (NKEYS * NKEYS) / 4;
            float4 acc0 = a[i0];
            float4 acc1 = a[i1];
            #pragma unroll
            for (int r = 1; r < RADJ; r++) {
                float4 v0 = a[i0 + r * stride];
                float4 v1 = a[i1 + r * stride];
                acc0.x += v0.x; acc0.y += v0.y; acc0.z += v0.z; acc0.w += v0.w;
                acc1.x += v1.x; acc1.y += v1.y; acc1.z += v1.z; acc1.w += v1.w;
            }
            ((float4*)g_adjsum)[i0] = acc0;
            ((float4*)g_adjsum)[i1] = acc1;
        }
    }

    grid_barrier(&s_sense, tid);

    // ================= PHASE B1: topk + softmax (one query/block), weights to global =================
    if (bid < Q) {
        const int q = bid;
        const int lane = tid & 31;
        #pragma unroll
        for (int j = 0; j < 2; j++) {
            int p = j * 256 + tid;
            float4 v = ((const float4*)(g_scores + q * NKEYS))[p];
            float4 n = ((const float4*)g_invn)[p];
            v.x *= n.x; v.y *= n.y; v.z *= n.z; v.w *= n.w;
            *(float4*)&sm.tk.sv[p * 4] = v;
        }
        __syncthreads();
        if (tid < 32) {
            float bestv[TOPK]; int besti[TOPK];
            #pragma unroll 1
            for (int t = 0; t < TOPK; t++) {
                float best = -1e30f; int bi = 0;
                #pragma unroll
                for (int j = 0; j < NKEYS / 32; j++) {
                    int i = j * 32 + lane;
                    float v = sm.tk.sv[i];
                    if (v > best) { best = v; bi = i; }
                }
                #pragma unroll
                for (int o = 16; o > 0; o >>= 1) {
                    float ov = __shfl_xor_sync(0xffffffffu, best, o);
                    int   oi = __shfl_xor_sync(0xffffffffu, bi, o);
                    if (ov > best || (ov == best && oi < bi)) { best = ov; bi = oi; }
                }
                bestv[t] = best; besti[t] = bi;
                if ((bi & 31) == lane) sm.tk.sv[bi] = -1e30f;
                __syncwarp();
            }
            if (lane == 0) {
                float m = bestv[0];
                float e[TOPK], sum = 0.f;
                #pragma unroll
                for (int t = 0; t < TOPK; t++) { e[t] = expf(bestv[t] - m); sum += e[t]; }
                float invs = 1.f / sum;
                #pragma unroll
                for (int t = 0; t < TOPK; t++) {
                    g_w[q * TOPK + t] = e[t] * invs;
                    g_idx[q * TOPK + t] = besti[t];
                }
            }
        }
    }
    if (bid == NB - 1 && tid == 0) atomicExch(&g_workA, 0u);   // reset for next launch

    grid_barrier(&s_sense, tid);

    // ================= PHASE B2: gather nei (512 units: query x col-half) =================
    for (int u = bid; u < 2 * Q; u += NB) {
        const int q = u >> 1;
        const int p = (u & 1) * 256 + tid;     // float4 col index
        float w[TOPK]; int id[TOPK];
        #pragma unroll
        for (int t = 0; t < TOPK; t++) { w[t] = g_w[q * TOPK + t]; id[t] = g_idx[q * TOPK + t]; }
        float4 acc = make_float4(0.f, 0.f, 0.f, 0.f);
        #pragma unroll
        for (int t = 0; t < TOPK; t++) {
            const float4 v = ((const float4*)(g_adjsum + (size_t)id[t] * NKEYS))[p];
            float wt = w[t];
            acc.x += wt * v.x; acc.y += wt * v.y; acc.z += wt * v.z; acc.w += wt * v.w;
        }
        ((float4*)(g_nei + q * NKEYS))[p] = acc;
    }

    grid_barrier(&s_sense, tid);

    // ================= PHASE C: out GEMM, 64q x 64d tiles, splitK 8 (384 units) =================
    if (bid < 384) {
        const int d0 = (bid % 12) * 64;
        const int q0 = ((bid / 12) & 3) * 64;
        const int z  = bid / 48;                 // 0..7
        const int kbase = z * (NKEYS / SPLITK);  // 256 K per split
        const int tx = tid & 15, ty = tid >> 4;
        unsigned long long acc2[4][2] = {};
        for (int kt = kbase; kt < kbase + NKEYS / SPLITK; kt += 32) {
            #pragma unroll
            for (int l = 0; l < 2; l++) {
                int f = tid + l * 256;
                int arow = f >> 3, ac4 = f & 7;
                float4 v = *(const float4*)(g_nei + (q0 + arow) * NKEYS + kt + ac4 * 4);
                sm.sc.As[ac4*4+0][arow] = v.x; sm.sc.As[ac4*4+1][arow] = v.y;
                sm.sc.As[ac4*4+2][arow] = v.z; sm.sc.As[ac4*4+3][arow] = v.w;
                int brow = f >> 4, bc4 = f & 15;
                float inv = g_invn[kt + brow];
                float4 u = *(const float4*)(kp + (kt + brow) * D + d0 + bc4 * 4);
                u.x *= inv; u.y *= inv; u.z *= inv; u.w *= inv;
                *(float4*)&sm.sc.Bs[brow][bc4 * 4] = u;
            }
            __syncthreads();
            #pragma unroll
            for (int kk = 0; kk < 32; kk++) {
                float4 a4 = *(const float4*)&sm.sc.As[kk][ty * 4];
                float4 b4 = *(const float4*)&sm.sc.Bs[kk][tx * 4];
                unsigned long long bp0 = ((const unsigned long long*)&b4)[0];
                unsigned long long bp1 = ((const unsigned long long*)&b4)[1];
                float av[4] = {a4.x, a4.y, a4.z, a4.w};
                #pragma unroll
                for (int i = 0; i < 4; i++) {
                    unsigned long long ap = pack_dup(av[i]);
                    ffma2(acc2[i][0], ap, bp0);
                    ffma2(acc2[i][1], ap, bp1);
                }
            }
            __syncthreads();
        }
        #pragma unroll
        for (int i = 0; i < 4; i++) {
            float4 v;
            *(unsigned long long*)&v.x = acc2[i][0];
            *(unsigned long long*)&v.z = acc2[i][1];
            *(float4*)(g_opart + ((size_t)z * Q + q0 + ty * 4 + i) * D + d0 + tx * 4) = v;
        }
    }

    grid_barrier(&s_sense, tid);

    // ================= PHASE D: reduce split-K partials =================
    for (int i = bid * 256 + tid; i < Q * D / 4; i += NB * 256) {
        const float4* p = (const float4*)g_opart;
        const int stride = (Q * D) / 4;
        float4 a = p[i];
        #pragma unroll
        for (int z = 1; z < SPLITK; z++) {
            float4 v = p[i + z * stride];
            a.x += v.x; a.y += v.y; a.z += v.z; a.w += v.w;
        }
        ((float4*)out)[i] = a;
    }
}

extern "C" void kernel_launch(void* const* d_in, const int* in_sizes, int n_in,
                              void* d_out, int out_size) {
    const float* positions = (const float*)d_in[0];   // (4,64,768)
    const float* keys_p    = (const float*)d_in[1];   // (2048,768)
    const float* adjacency = (const float*)d_in[2];   // (12,2048,2048)
    float* out = (float*)d_out;                       // (4,64,768)

    mega_kernel<<<NB, 256>>>(positions, keys_p, adjacency, out);
}

// round 16
// speedup vs baseline: 1.0578x; 1.0578x over previous
#include <cuda_runtime.h>
#include <math.h>

#define Q 256      // B*P = 4*64
#define D 768
#define NKEYS 2048
#define RADJ 12
#define TOPK 16
#define SPLITK 8
#define NB 444     // 148 SMs x occupancy 3 — guaranteed co-resident

// ---------------- scratch (static device memory; no allocations) ----------------
__device__ float g_invn[NKEYS];
__device__ float g_adjsum[NKEYS * NKEYS];    // 16.8 MB
__device__ float g_scores[Q * NKEYS];        // raw dots
__device__ float g_w[Q * TOPK];
__device__ int   g_idx[Q * TOPK];
__device__ float g_nei[Q * NKEYS];
__device__ float g_opart[SPLITK * Q * D];    // 6.3 MB

// grid barrier + work-steal state (self-resetting across launches)
__device__ unsigned g_cnt = 0;
__device__ volatile unsigned g_sense = 0;
__device__ unsigned g_workA = 0;

// packed f32x2 FMA
__device__ __forceinline__ void ffma2(unsigned long long& c, unsigned long long a, unsigned long long b) {
    asm("fma.rn.f32x2 %0, %1, %2, %0;" : "+l"(c) : "l"(a), "l"(b));
}
__device__ __forceinline__ unsigned long long pack_dup(float a) {
    unsigned long long r;
    asm("mov.b64 %0, {%1, %1};" : "=l"(r) : "r"(__float_as_uint(a)));
    return r;
}

union SMem {
    struct { float As[32][68]; float Bs[32][68]; } sc;     // GEMM tiles 17.4 KB
    struct { float sv[NKEYS]; float sw[TOPK]; int sid[TOPK]; } tk;  // topk 8.2 KB
};

__device__ __forceinline__ void grid_barrier(unsigned* s_sense, int tid) {
    __syncthreads();
    if (tid == 0) {
        unsigned want = *s_sense ^ 1u;
        __threadfence();
        unsigned old = atomicAdd(&g_cnt, 1u);
        if (old == NB - 1) {
            atomicExch(&g_cnt, 0u);
            __threadfence();
            g_sense = want;                 // release
        } else {
            while (g_sense != want) { __nanosleep(32); }
        }
        __threadfence();
        *s_sense = want;
    }
    __syncthreads();
}

__global__ __launch_bounds__(256, 3) void mega_kernel(const float* __restrict__ A,
                                                      const float* __restrict__ kp,
                                                      const float* __restrict__ adj,
                                                      float* __restrict__ out) {
    __shared__ SMem sm;
    __shared__ unsigned s_sense;
    const int tid = threadIdx.x;
    const int bid = blockIdx.x;
    if (tid == 0) s_sense = g_sense;
    __syncthreads();

    // ================= PHASE A: scores GEMM + invn + adjsum (PER-WARP work-stealing) =================
    if (bid < 128) {
        // scores GEMM (NT) 64x64 tile, register double-buffered (R13 shape)
        const int n0 = (bid & 31) * 64;
        const int m0 = (bid >> 5) * 64;
        const int tx = tid & 15, ty = tid >> 4;
        const int lrow = tid >> 3, lc4 = tid & 7;
        const int lrow1 = (tid + 256) >> 3, lc41 = (tid + 256) & 7;
        unsigned long long acc2[4][2] = {};
        float4 ra0, ra1, rb0, rb1;
        ra0 = *(const float4*)(A + (m0 + lrow) * D + 0 + lc4 * 4);
        rb0 = *(const float4*)(kp + (n0 + lrow) * D + 0 + lc4 * 4);
        ra1 = *(const float4*)(A + (m0 + lrow1) * D + 0 + lc41 * 4);
        rb1 = *(const float4*)(kp + (n0 + lrow1) * D + 0 + lc41 * 4);
        for (int kt = 0; kt < D; kt += 32) {
            __syncthreads();
            sm.sc.As[lc4*4+0][lrow] = ra0.x; sm.sc.As[lc4*4+1][lrow] = ra0.y;
            sm.sc.As[lc4*4+2][lrow] = ra0.z; sm.sc.As[lc4*4+3][lrow] = ra0.w;
            sm.sc.Bs[lc4*4+0][lrow] = rb0.x; sm.sc.Bs[lc4*4+1][lrow] = rb0.y;
            sm.sc.Bs[lc4*4+2][lrow] = rb0.z; sm.sc.Bs[lc4*4+3][lrow] = rb0.w;
            sm.sc.As[lc41*4+0][lrow1] = ra1.x; sm.sc.As[lc41*4+1][lrow1] = ra1.y;
            sm.sc.As[lc41*4+2][lrow1] = ra1.z; sm.sc.As[lc41*4+3][lrow1] = ra1.w;
            sm.sc.Bs[lc41*4+0][lrow1] = rb1.x; sm.sc.Bs[lc41*4+1][lrow1] = rb1.y;
            sm.sc.Bs[lc41*4+2][lrow1] = rb1.z; sm.sc.Bs[lc41*4+3][lrow1] = rb1.w;
            __syncthreads();
            if (kt + 32 < D) {
                ra0 = *(const float4*)(A + (m0 + lrow) * D + kt + 32 + lc4 * 4);
                rb0 = *(const float4*)(kp + (n0 + lrow) * D + kt + 32 + lc4 * 4);
                ra1 = *(const float4*)(A + (m0 + lrow1) * D + kt + 32 + lc41 * 4);
                rb1 = *(const float4*)(kp + (n0 + lrow1) * D + kt + 32 + lc41 * 4);
            }
            #pragma unroll
            for (int kk = 0; kk < 32; kk++) {
                float4 a4 = *(const float4*)&sm.sc.As[kk][ty * 4];
                float4 b4 = *(const float4*)&sm.sc.Bs[kk][tx * 4];
                unsigned long long bp0 = ((const unsigned long long*)&b4)[0];
                unsigned long long bp1 = ((const unsigned long long*)&b4)[1];
                float av[4] = {a4.x, a4.y, a4.z, a4.w};
                #pragma unroll
                for (int i = 0; i < 4; i++) {
                    unsigned long long ap = pack_dup(av[i]);
                    ffma2(acc2[i][0], ap, bp0);
                    ffma2(acc2[i][1], ap, bp1);
                }
            }
        }
        #pragma unroll
        for (int i = 0; i < 4; i++) {
            float4 v;
            *(unsigned long long*)&v.x = acc2[i][0];
            *(unsigned long long*)&v.z = acc2[i][1];
            *(float4*)(g_scores + (m0 + ty * 4 + i) * NKEYS + n0 + tx * 4) = v;
        }
    } else if (bid < 384) {
        // key inverse norms: blocks 128..383, 8 warps x 256 blocks = 2048 rows
        const int row = (bid - 128) * 8 + (tid >> 5);
        const int lane = tid & 31;
        const float* src = kp + row * D;
        float s = 0.f;
        #pragma unroll
        for (int j = 0; j < D / 32; j++) { float v = src[j * 32 + lane]; s += v * v; }
        #pragma unroll
        for (int o = 16; o > 0; o >>= 1) s += __shfl_xor_sync(0xffffffffu, s, o);
        if (lane == 0) g_invn[row] = rsqrtf(s + 1e-12f);
    }
    // ALL warps: independent per-warp stealing of 4KB adjsum units — no block syncs.
    {
        const int lane = tid & 31;
        const float4* a = (const float4*)adj;
        const int stride = (NKEYS * NKEYS) / 4;
        for (;;) {
            unsigned u = 0;
            if (lane == 0) u = atomicAdd(&g_workA, 1u);
            u = __shfl_sync(0xffffffffu, u, 0);
            if (u >= 4096u) break;
            const int base = (int)u * 256 + lane;       // 256 f4 per unit, 8 iters/lane
            #pragma unroll
            for (int it = 0; it < 8; it += 2) {
                const int i0 = base + it * 32;
                const int i1 = i0 + 32;
                float4 acc0 = a[i0];
                float4 acc1 = a[i1];
                #pragma unroll
                for (int r = 1; r < RADJ; r++) {
                    float4 v0 = a[i0 + r * stride];
                    float4 v1 = a[i1 + r * stride];
                    acc0.x += v0.x; acc0.y += v0.y; acc0.z += v0.z; acc0.w += v0.w;
                    acc1.x += v1.x; acc1.y += v1.y; acc1.z += v1.z; acc1.w += v1.w;
                }
                ((float4*)g_adjsum)[i0] = acc0;
                ((float4*)g_adjsum)[i1] = acc1;
            }
        }
    }

    grid_barrier(&s_sense, tid);

    // ================= PHASE B1: topk + softmax (one query/block) =================
    if (bid < Q) {
        const int q = bid;
        const int lane = tid & 31;
        #pragma unroll
        for (int j = 0; j < 2; j++) {
            int p = j * 256 + tid;
            float4 v = ((const float4*)(g_scores + q * NKEYS))[p];
            float4 n = ((const float4*)g_invn)[p];
            v.x *= n.x; v.y *= n.y; v.z *= n.z; v.w *= n.w;
            *(float4*)&sm.tk.sv[p * 4] = v;
        }
        __syncthreads();
        if (tid < 32) {
            float bestv[TOPK]; int besti[TOPK];
            #pragma unroll 1
            for (int t = 0; t < TOPK; t++) {
                float best = -1e30f; int bi = 0;
                #pragma unroll
                for (int j = 0; j < NKEYS / 32; j++) {
                    int i = j * 32 + lane;
                    float v = sm.tk.sv[i];
                    if (v > best) { best = v; bi = i; }
                }
                #pragma unroll
                for (int o = 16; o > 0; o >>= 1) {
                    float ov = __shfl_xor_sync(0xffffffffu, best, o);
                    int   oi = __shfl_xor_sync(0xffffffffu, bi, o);
                    if (ov > best || (ov == best && oi < bi)) { best = ov; bi = oi; }
                }
                bestv[t] = best; besti[t] = bi;
                if ((bi & 31) == lane) sm.tk.sv[bi] = -1e30f;
                __syncwarp();
            }
            if (lane == 0) {
                float m = bestv[0];
                float e[TOPK], sum = 0.f;
                #pragma unroll
                for (int t = 0; t < TOPK; t++) { e[t] = expf(bestv[t] - m); sum += e[t]; }
                float invs = 1.f / sum;
                #pragma unroll
                for (int t = 0; t < TOPK; t++) {
                    g_w[q * TOPK + t] = e[t] * invs;
                    g_idx[q * TOPK + t] = besti[t];
                }
            }
        }
    }
    if (bid == NB - 1 && tid == 0) atomicExch(&g_workA, 0u);   // reset for next launch

    grid_barrier(&s_sense, tid);

    // ================= PHASE B2: gather nei (512 units: query x col-half) =================
    for (int u = bid; u < 2 * Q; u += NB) {
        const int q = u >> 1;
        const int p = (u & 1) * 256 + tid;     // float4 col index
        float w[TOPK]; int id[TOPK];
        #pragma unroll
        for (int t = 0; t < TOPK; t++) { w[t] = g_w[q * TOPK + t]; id[t] = g_idx[q * TOPK + t]; }
        float4 acc = make_float4(0.f, 0.f, 0.f, 0.f);
        #pragma unroll
        for (int t = 0; t < TOPK; t++) {
            const float4 v = ((const float4*)(g_adjsum + (size_t)id[t] * NKEYS))[p];
            float wt = w[t];
            acc.x += wt * v.x; acc.y += wt * v.y; acc.z += wt * v.z; acc.w += wt * v.w;
        }
        ((float4*)(g_nei + q * NKEYS))[p] = acc;
    }

    grid_barrier(&s_sense, tid);

    // ================= PHASE C: out GEMM, 64q x 64d tiles, splitK 8 (384 units) =================
    if (bid < 384) {
        const int d0 = (bid % 12) * 64;
        const int q0 = ((bid / 12) & 3) * 64;
        const int z  = bid / 48;                 // 0..7
        const int kbase = z * (NKEYS / SPLITK);  // 256 K per split
        const int tx = tid & 15, ty = tid >> 4;
        unsigned long long acc2[4][2] = {};
        for (int kt = kbase; kt < kbase + NKEYS / SPLITK; kt += 32) {
            #pragma unroll
            for (int l = 0; l < 2; l++) {
                int f = tid + l * 256;
                int arow = f >> 3, ac4 = f & 7;
                float4 v = *(const float4*)(g_nei + (q0 + arow) * NKEYS + kt + ac4 * 4);
                sm.sc.As[ac4*4+0][arow] = v.x; sm.sc.As[ac4*4+1][arow] = v.y;
                sm.sc.As[ac4*4+2][arow] = v.z; sm.sc.As[ac4*4+3][arow] = v.w;
                int brow = f >> 4, bc4 = f & 15;
                float inv = g_invn[kt + brow];
                float4 u = *(const float4*)(kp + (kt + brow) * D + d0 + bc4 * 4);
                u.x *= inv; u.y *= inv; u.z *= inv; u.w *= inv;
                *(float4*)&sm.sc.Bs[brow][bc4 * 4] = u;
            }
            __syncthreads();
            #pragma unroll
            for (int kk = 0; kk < 32; kk++) {
                float4 a4 = *(const float4*)&sm.sc.As[kk][ty * 4];
                float4 b4 = *(const float4*)&sm.sc.Bs[kk][tx * 4];
                unsigned long long bp0 = ((const unsigned long long*)&b4)[0];
                unsigned long long bp1 = ((const unsigned long long*)&b4)[1];
                float av[4] = {a4.x, a4.y, a4.z, a4.w};
                #pragma unroll
                for (int i = 0; i < 4; i++) {
                    unsigned long long ap = pack_dup(av[i]);
                    ffma2(acc2[i][0], ap, bp0);
                    ffma2(acc2[i][1], ap, bp1);
                }
            }
            __syncthreads();
        }
        #pragma unroll
        for (int i = 0; i < 4; i++) {
            float4 v;
            *(unsigned long long*)&v.x = acc2[i][0];
            *(unsigned long long*)&v.z = acc2[i][1];
            *(float4*)(g_opart + ((size_t)z * Q + q0 + ty * 4 + i) * D + d0 + tx * 4) = v;
        }
    }

    grid_barrier(&s_sense, tid);

    // ================= PHASE D: reduce split-K partials =================
    for (int i = bid * 256 + tid; i < Q * D / 4; i += NB * 256) {
        const float4* p = (const float4*)g_opart;
        const int stride = (Q * D) / 4;
        float4 a = p[i];
        #pragma unroll
        for (int z = 1; z < SPLITK; z++) {
            float4 v = p[i + z * stride];
            a.x += v.x; a.y += v.y; a.z += v.z; a.w += v.w;
        }
        ((float4*)out)[i] = a;
    }
}

extern "C" void kernel_launch(void* const* d_in, const int* in_sizes, int n_in,
                              void* d_out, int out_size) {
    const float* positions = (const float*)d_in[0];   // (4,64,768)
    const float* keys_p    = (const float*)d_in[1];   // (2048,768)
    const float* adjacency = (const float*)d_in[2];   // (12,2048,2048)
    float* out = (float*)d_out;                       // (4,64,768)

    mega_kernel<<<NB, 256>>>(positions, keys_p, adjacency, out);
}